// round 2
// baseline (speedup 1.0000x reference)
#include <cuda_runtime.h>
#include <math.h>

#define EPSV 1e-5f

// ---------------- scratch (static device allocations only) ----------------
__device__ float g_qkv[128*256*128];          // [bh][o][l]        16 MB
__device__ float g_qk[128*16*128*128];        // [bh*16+g][i][j]  134 MB
__device__ float g_O[128*256*128];            // [bh][ch2][i]      16 MB
__device__ float g_qkv_sum[256], g_qkv_sq[256];
__device__ float g_sim_sum[48],  g_sim_sq[48];
__device__ float g_out_sum[256], g_out_sq[256];
__device__ float g_qkv_a[256], g_qkv_b[256];
__device__ float g_sim_scale[48];
__device__ float g_out_a[256], g_out_b[256];

// ---------------- K0: zero stats ----------------
__global__ void k_zero(){
  int t = threadIdx.x;
  if (t < 256){ g_qkv_sum[t]=0.f; g_qkv_sq[t]=0.f; g_out_sum[t]=0.f; g_out_sq[t]=0.f; }
  if (t < 48){  g_sim_sum[t]=0.f; g_sim_sq[t]=0.f; }
}

// ---------------- K1: qkv = W_qkv @ x  (per bh), + channel stats ----------------
// grid (2, 128): blockIdx.x = o-tile of 128, blockIdx.y = bh. 256 threads.
__global__ __launch_bounds__(256) void k_qkv(const float* __restrict__ x,
                                             const float* __restrict__ Wq){
  extern __shared__ float sm[];
  float* Ws = sm;            // [c][o_local] pitch 132
  float* Xs = sm + 128*132;  // [c][l]       pitch 132
  const int bh = blockIdx.y, ot = blockIdx.x;
  const int b = bh >> 6, h = bh & 63;
  const int tid = threadIdx.x;
  for (int idx = tid; idx < 16384; idx += 256){
    int r = idx >> 7, c2 = idx & 127;
    Ws[c2*132 + r] = Wq[(ot*128 + r)*128 + c2];
    Xs[r*132 + c2] = x[(((b*128 + r)*64) + h)*128 + c2];
  }
  __syncthreads();
  const int to = tid >> 4, tl = tid & 15;
  float acc[8][8];
  #pragma unroll
  for (int u=0;u<8;u++){
    #pragma unroll
    for (int v=0;v<8;v++) acc[u][v]=0.f;
  }
  const float* wa = Ws + to*8;
  const float* xb = Xs + tl*8;
  for (int c = 0; c < 128; c++){
    float4 A0 = *(const float4*)(wa + c*132);
    float4 A1 = *(const float4*)(wa + c*132 + 4);
    float4 B0 = *(const float4*)(xb + c*132);
    float4 B1 = *(const float4*)(xb + c*132 + 4);
    float a[8]  = {A0.x,A0.y,A0.z,A0.w,A1.x,A1.y,A1.z,A1.w};
    float bb[8] = {B0.x,B0.y,B0.z,B0.w,B1.x,B1.y,B1.z,B1.w};
    #pragma unroll
    for (int u=0;u<8;u++){
      #pragma unroll
      for (int v=0;v<8;v++) acc[u][v] = fmaf(a[u], bb[v], acc[u][v]);
    }
  }
  float s[8], q[8];
  const int obase = ot*128 + to*8;
  #pragma unroll
  for (int u=0;u<8;u++){
    float* dst = g_qkv + ((size_t)bh*256 + obase + u)*128 + tl*8;
    *(float4*)dst     = make_float4(acc[u][0],acc[u][1],acc[u][2],acc[u][3]);
    *(float4*)(dst+4) = make_float4(acc[u][4],acc[u][5],acc[u][6],acc[u][7]);
    float ls=0.f, lq=0.f;
    #pragma unroll
    for (int v=0;v<8;v++){ ls += acc[u][v]; lq += acc[u][v]*acc[u][v]; }
    s[u]=ls; q[u]=lq;
  }
  #pragma unroll
  for (int off=8; off>0; off>>=1){
    #pragma unroll
    for (int u=0;u<8;u++){
      s[u] += __shfl_down_sync(0xffffffffu, s[u], off, 16);
      q[u] += __shfl_down_sync(0xffffffffu, q[u], off, 16);
    }
  }
  if (tl == 0){
    #pragma unroll
    for (int u=0;u<8;u++){
      atomicAdd(&g_qkv_sum[obase+u], s[u]);
      atomicAdd(&g_qkv_sq [obase+u], q[u]);
    }
  }
}

// ---------------- K2: finalize qkv BN -> scale/shift per channel ----------------
__global__ void k_fin_qkv(const float* __restrict__ gm, const float* __restrict__ bt){
  int o = threadIdx.x;
  float m = g_qkv_sum[o] * (1.f/16384.f);
  float v = g_qkv_sq[o] * (1.f/16384.f) - m*m;
  float a = gm[o] * rsqrtf(v + EPSV);
  g_qkv_a[o] = a;
  g_qkv_b[o] = bt[o] - m*a;
}

// ---------------- K3: build qe/ke in smem, qk = qe^T @ ke, + sim stats ----------
// grid (16, 128): blockIdx.x = g, blockIdx.y = bh. 256 threads.
__global__ __launch_bounds__(256) void k_qk(const float* __restrict__ rel){
  extern __shared__ float sm[];
  float* qe  = sm;                 // [x][i] pitch 132
  float* ke  = sm + 128*132;       // [x][j] pitch 132
  float* re  = ke + 128*132;       // [16][256]  (rows 0-3 q, 4-7 k, 8-15 v unused here)
  float* qn  = re + 16*256;        // [8][128] normalized q(0-3),k(4-7)
  float* red = qn + 8*128;         // 32 floats
  const int g = blockIdx.x, bh = blockIdx.y;
  const int tid = threadIdx.x;
  for (int idx = tid; idx < 16*255; idx += 256)
    re[(idx/255)*256 + (idx%255)] = rel[idx];
  for (int idx = tid; idx < 1024; idx += 256){
    int a = idx >> 7, xx = idx & 127;
    int o = g*16 + a;       // a<4: q channels, a in 4..7: k channels
    qn[idx] = g_qkv[((size_t)bh*256 + o)*128 + xx] * g_qkv_a[o] + g_qkv_b[o];
  }
  __syncthreads();
  // build qe/ke: qe[x][i] = sum_a qn[a][x] * rel[a][x-i+127]
  float sqe=0.f, qqe=0.f, ske=0.f, qke=0.f;
  for (int idx = tid; idx < 16384; idx += 256){
    int xx = idx >> 7, i = idx & 127;
    int off = xx - i + 127;
    float e1 = 0.f, e2 = 0.f;
    #pragma unroll
    for (int a=0;a<4;a++){
      e1 = fmaf(qn[a*128+xx],     re[a*256+off],     e1);
      e2 = fmaf(qn[(4+a)*128+xx], re[(4+a)*256+off], e2);
    }
    qe[xx*132+i] = e1; ke[xx*132+i] = e2;
    sqe += e1; qqe += e1*e1; ske += e2; qke += e2*e2;
  }
  #pragma unroll
  for (int off=16; off>0; off>>=1){
    sqe += __shfl_down_sync(0xffffffffu, sqe, off);
    qqe += __shfl_down_sync(0xffffffffu, qqe, off);
    ske += __shfl_down_sync(0xffffffffu, ske, off);
    qke += __shfl_down_sync(0xffffffffu, qke, off);
  }
  const int w = tid>>5, ln = tid&31;
  if (ln==0){ red[w]=sqe; red[8+w]=qqe; red[16+w]=ske; red[24+w]=qke; }
  __syncthreads();   // also makes qe/ke visible for GEMM
  if (tid==0){
    float t0=0,t1=0,t2=0,t3=0;
    for (int k2=0;k2<8;k2++){ t0+=red[k2]; t1+=red[8+k2]; t2+=red[16+k2]; t3+=red[24+k2]; }
    atomicAdd(&g_sim_sum[16+g], t0); atomicAdd(&g_sim_sq[16+g], t1);
    atomicAdd(&g_sim_sum[32+g], t2); atomicAdd(&g_sim_sq[32+g], t3);
  }
  // GEMM: qk[i][j] = sum_x qe[x][i]*ke[x][j]
  const int ti = tid>>4, tj = tid&15;
  float acc[8][8];
  #pragma unroll
  for (int u=0;u<8;u++){
    #pragma unroll
    for (int v=0;v<8;v++) acc[u][v]=0.f;
  }
  const float* pa = qe + ti*8;
  const float* pb = ke + tj*8;
  for (int xx=0; xx<128; xx++){
    float4 A0 = *(const float4*)(pa + xx*132);
    float4 A1 = *(const float4*)(pa + xx*132 + 4);
    float4 B0 = *(const float4*)(pb + xx*132);
    float4 B1 = *(const float4*)(pb + xx*132 + 4);
    float a[8]  = {A0.x,A0.y,A0.z,A0.w,A1.x,A1.y,A1.z,A1.w};
    float bb[8] = {B0.x,B0.y,B0.z,B0.w,B1.x,B1.y,B1.z,B1.w};
    #pragma unroll
    for (int u=0;u<8;u++){
      #pragma unroll
      for (int v=0;v<8;v++) acc[u][v] = fmaf(a[u], bb[v], acc[u][v]);
    }
  }
  float* dst0 = g_qk + ((size_t)(bh*16+g))*16384;
  float sqk=0.f, qqk=0.f;
  #pragma unroll
  for (int u=0;u<8;u++){
    float* dst = dst0 + (ti*8+u)*128 + tj*8;
    *(float4*)dst     = make_float4(acc[u][0],acc[u][1],acc[u][2],acc[u][3]);
    *(float4*)(dst+4) = make_float4(acc[u][4],acc[u][5],acc[u][6],acc[u][7]);
    #pragma unroll
    for (int v=0;v<8;v++){ sqk += acc[u][v]; qqk += acc[u][v]*acc[u][v]; }
  }
  #pragma unroll
  for (int off=16; off>0; off>>=1){
    sqk += __shfl_down_sync(0xffffffffu, sqk, off);
    qqk += __shfl_down_sync(0xffffffffu, qqk, off);
  }
  __syncthreads();   // protect red reuse
  if (ln==0){ red[w]=sqk; red[8+w]=qqk; }
  __syncthreads();
  if (tid==0){
    float t0=0,t1=0;
    for (int k2=0;k2<8;k2++){ t0+=red[k2]; t1+=red[8+k2]; }
    atomicAdd(&g_sim_sum[g], t0); atomicAdd(&g_sim_sq[g], t1);
  }
}

// ---------------- K4: finalize sim BN scales (means cancel in softmax) ---------
__global__ void k_fin_sim(const float* __restrict__ gm){
  int c = threadIdx.x;
  if (c < 48){
    const float ninv = 1.f/2097152.f;
    float m = g_sim_sum[c]*ninv;
    float v = g_sim_sq[c]*ninv - m*m;
    g_sim_scale[c] = gm[c]*rsqrtf(v+EPSV);
  }
}

// ---------------- K5: softmax + am/ame + out stats ----------------
// grid (16, 128). 256 threads = 8 warps, warp w owns rows i = w*16 + r.
__global__ __launch_bounds__(256) void k_attn(const float* __restrict__ rel){
  extern __shared__ float sm[];
  float* re    = sm;            // [16][256]
  float* qn    = re + 16*256;   // [8][128]  q(0-3), k(4-7) normalized
  float* vs    = qn + 1024;     // [8][128]  v normalized
  float* stage = vs + 1024;     // 8 warps * 16*33
  const int g = blockIdx.x, bh = blockIdx.y;
  const int tid = threadIdx.x;
  for (int idx = tid; idx < 16*255; idx += 256)
    re[(idx/255)*256 + (idx%255)] = rel[idx];
  for (int idx = tid; idx < 1024; idx += 256){
    int a = idx >> 7, xx = idx & 127;
    int oq = g*16 + a;
    qn[idx] = g_qkv[((size_t)bh*256 + oq)*128 + xx]*g_qkv_a[oq] + g_qkv_b[oq];
    int ov = g*16 + 8 + a;
    vs[idx] = g_qkv[((size_t)bh*256 + ov)*128 + xx]*g_qkv_a[ov] + g_qkv_b[ov];
  }
  __syncthreads();
  const float s0 = g_sim_scale[g], s1 = g_sim_scale[16+g], s2 = g_sim_scale[32+g];
  const int w = tid>>5, ln = tid&31;
  const float* qkrow0 = g_qk + ((size_t)(bh*16+g))*16384;
  float* st = stage + w*(16*33);
  float osum = 0.f, osq = 0.f;
  for (int r = 0; r < 16; r++){
    const int i = w*16 + r;
    float4 qk4 = *(const float4*)(qkrow0 + i*128 + ln*4);
    float qkl[4] = {qk4.x, qk4.y, qk4.z, qk4.w};
    float qi[4], ki[4];
    #pragma unroll
    for (int a=0;a<4;a++){ qi[a]=qn[a*128+i]; ki[a]=qn[(4+a)*128+i]; }
    float p[4]; float mx = -1e30f;
    #pragma unroll
    for (int jj=0;jj<4;jj++){
      int j = ln*4 + jj;
      int off = i - j + 127;
      float e1=0.f, e2=0.f;
      #pragma unroll
      for (int a=0;a<4;a++){
        e1 = fmaf(qi[a], re[a*256+off],     e1);
        e2 = fmaf(ki[a], re[(4+a)*256+off], e2);
      }
      float lg = qkl[jj]*s0 + e1*s1 + e2*s2;
      p[jj] = lg;
      mx = fmaxf(mx, lg);
    }
    #pragma unroll
    for (int o2=16; o2>0; o2>>=1) mx = fmaxf(mx, __shfl_xor_sync(0xffffffffu, mx, o2));
    float ss = 0.f;
    #pragma unroll
    for (int jj=0;jj<4;jj++){ p[jj] = __expf(p[jj]-mx); ss += p[jj]; }
    #pragma unroll
    for (int o2=16; o2>0; o2>>=1) ss += __shfl_xor_sync(0xffffffffu, ss, o2);
    float inv = 1.f/ss;
    #pragma unroll
    for (int jj=0;jj<4;jj++) p[jj] *= inv;
    // partial am/ame over this lane's 4 j's, staged to smem for cross-lane sum
    #pragma unroll
    for (int c=0;c<8;c++){
      float am=0.f, ae=0.f;
      #pragma unroll
      for (int jj=0;jj<4;jj++){
        int j = ln*4 + jj;
        am = fmaf(p[jj], vs[c*128+j], am);
        ae = fmaf(p[jj], re[(8+c)*256 + (i-j+127)], ae);
      }
      st[(2*c)*33   + ln] = am;
      st[(2*c+1)*33 + ln] = ae;
    }
    __syncwarp();
    if (ln < 16){
      const float* rowp = st + ln*33;
      float outv = 0.f;
      #pragma unroll
      for (int qq=0; qq<32; qq++) outv += rowp[qq];
      g_O[((size_t)bh*256 + g*16 + ln)*128 + i] = outv;  // ch2 = g*16 + (2c+t)
      osum += outv; osq += outv*outv;
    }
    __syncwarp();
  }
  if (ln < 16){
    atomicAdd(&g_out_sum[g*16+ln], osum);
    atomicAdd(&g_out_sq [g*16+ln], osq);
  }
}

// ---------------- K6: finalize out BN ----------------
__global__ void k_fin_out(const float* __restrict__ gm, const float* __restrict__ bt){
  int o = threadIdx.x;
  float m = g_out_sum[o]*(1.f/16384.f);
  float v = g_out_sq[o]*(1.f/16384.f) - m*m;
  float a = gm[o]*rsqrtf(v+EPSV);
  g_out_a[o]=a; g_out_b[o]=bt[o]-m*a;
}

// ---------------- K7: normalize, pair-sum, transpose to (B,128,H,W) -----------
__global__ __launch_bounds__(256) void k_final(float* __restrict__ out){
  int t = blockIdx.x*256 + threadIdx.x;      // one float4 per thread
  int lq = t & 31;
  int h  = (t>>5) & 63;
  int m  = (t>>11) & 127;
  int b  = (t>>18) & 1;
  int bh = b*64 + h;
  int ch = 2*m;
  const float4 am = *(const float4*)(g_O + ((size_t)bh*256 + ch  )*128 + lq*4);
  const float4 ae = *(const float4*)(g_O + ((size_t)bh*256 + ch+1)*128 + lq*4);
  float a0=g_out_a[ch], b0=g_out_b[ch], a1=g_out_a[ch+1], b1=g_out_b[ch+1];
  float4 rr;
  rr.x = fmaf(am.x,a0,b0) + fmaf(ae.x,a1,b1);
  rr.y = fmaf(am.y,a0,b0) + fmaf(ae.y,a1,b1);
  rr.z = fmaf(am.z,a0,b0) + fmaf(ae.z,a1,b1);
  rr.w = fmaf(am.w,a0,b0) + fmaf(ae.w,a1,b1);
  ((float4*)out)[t] = rr;
}

// ---------------- host launcher ----------------
extern "C" void kernel_launch(void* const* d_in, const int* in_sizes, int n_in,
                              void* d_out, int out_size){
  (void)in_sizes; (void)n_in; (void)out_size;
  const float* x  = (const float*)d_in[0];
  const float* Wq = (const float*)d_in[1];
  const float* gq = (const float*)d_in[2];
  const float* bq = (const float*)d_in[3];
  const float* re = (const float*)d_in[4];
  const float* gs = (const float*)d_in[5];
  // d_in[6] = beta_sim: provably cancels in softmax (constant in j per channel)
  const float* go = (const float*)d_in[7];
  const float* bo = (const float*)d_in[8];

  const int smem1 = 2*128*132*4;                                   // 135168
  const int smem3 = (2*128*132 + 16*256 + 8*128 + 32)*4;           // 155776
  const int smem5 = (16*256 + 1024 + 1024 + 8*16*33)*4;            // 41472
  cudaFuncSetAttribute(k_qkv, cudaFuncAttributeMaxDynamicSharedMemorySize, smem1);
  cudaFuncSetAttribute(k_qk,  cudaFuncAttributeMaxDynamicSharedMemorySize, smem3);

  k_zero   <<<1,256>>>();
  k_qkv    <<<dim3(2,128),256,smem1>>>(x, Wq);
  k_fin_qkv<<<1,256>>>(gq,bq);
  k_qk     <<<dim3(16,128),256,smem3>>>(re);
  k_fin_sim<<<1,64>>>(gs);
  k_attn   <<<dim3(16,128),256,smem5>>>(re);
  k_fin_out<<<1,256>>>(go,bo);
  k_final  <<<2048,256>>>((float*)d_out);
}

// round 6
// speedup vs baseline: 1.3342x; 1.3342x over previous
#include <cuda_runtime.h>
#include <math.h>

#define EPSV 1e-5f

// ---------------- scratch (static device allocations only) ----------------
__device__ float g_qkv[128*256*128];          // [bh][o][l]        16 MB
__device__ float g_qk[128*16*128*128];        // [bh*16+g][i][j]  134 MB
__device__ float g_O[128*256*128];            // [bh][ch2][i]      16 MB
__device__ float g_qkv_sum[256], g_qkv_sq[256];
__device__ float g_sim_sum[48],  g_sim_sq[48];
__device__ float g_out_sum[256], g_out_sq[256];
__device__ float g_qkv_a[256], g_qkv_b[256];
__device__ float g_sim_scale[48];
__device__ float g_out_a[256], g_out_b[256];

__device__ __forceinline__ unsigned cvt_tf32(float v){
  unsigned r; asm("cvt.rna.tf32.f32 %0, %1;" : "=r"(r) : "f"(v)); return r;
}
__device__ __forceinline__ void mma8(float* d, const unsigned* a, const unsigned* b){
  asm volatile("mma.sync.aligned.m16n8k8.row.col.f32.tf32.tf32.f32 "
    "{%0,%1,%2,%3},{%4,%5,%6,%7},{%8,%9},{%0,%1,%2,%3};"
    : "+f"(d[0]),"+f"(d[1]),"+f"(d[2]),"+f"(d[3])
    : "r"(a[0]),"r"(a[1]),"r"(a[2]),"r"(a[3]),"r"(b[0]),"r"(b[1]));
}

// ---------------- K0: zero stats ----------------
__global__ void k_zero(){
  int t = threadIdx.x;
  if (t < 256){ g_qkv_sum[t]=0.f; g_qkv_sq[t]=0.f; g_out_sum[t]=0.f; g_out_sq[t]=0.f; }
  if (t < 48){  g_sim_sum[t]=0.f; g_sim_sq[t]=0.f; }
}

// ---------------- K1: qkv = W_qkv @ x  (per bh), + channel stats ----------------
__global__ __launch_bounds__(256) void k_qkv(const float* __restrict__ x,
                                             const float* __restrict__ Wq){
  extern __shared__ float sm[];
  float* Ws = sm;            // [c][o_local] pitch 132
  float* Xs = sm + 128*132;  // [c][l]       pitch 132
  const int bh = blockIdx.y, ot = blockIdx.x;
  const int b = bh >> 6, h = bh & 63;
  const int tid = threadIdx.x;
  for (int idx = tid; idx < 16384; idx += 256){
    int r = idx >> 7, c2 = idx & 127;
    Ws[c2*132 + r] = Wq[(ot*128 + r)*128 + c2];
    Xs[r*132 + c2] = x[(((b*128 + r)*64) + h)*128 + c2];
  }
  __syncthreads();
  const int to = tid >> 4, tl = tid & 15;
  float acc[8][8];
  #pragma unroll
  for (int u=0;u<8;u++){
    #pragma unroll
    for (int v=0;v<8;v++) acc[u][v]=0.f;
  }
  const float* wa = Ws + to*8;
  const float* xb = Xs + tl*8;
  for (int c = 0; c < 128; c++){
    float4 A0 = *(const float4*)(wa + c*132);
    float4 A1 = *(const float4*)(wa + c*132 + 4);
    float4 B0 = *(const float4*)(xb + c*132);
    float4 B1 = *(const float4*)(xb + c*132 + 4);
    float a[8]  = {A0.x,A0.y,A0.z,A0.w,A1.x,A1.y,A1.z,A1.w};
    float bb[8] = {B0.x,B0.y,B0.z,B0.w,B1.x,B1.y,B1.z,B1.w};
    #pragma unroll
    for (int u=0;u<8;u++){
      #pragma unroll
      for (int v=0;v<8;v++) acc[u][v] = fmaf(a[u], bb[v], acc[u][v]);
    }
  }
  float s[8], q[8];
  const int obase = ot*128 + to*8;
  #pragma unroll
  for (int u=0;u<8;u++){
    float* dst = g_qkv + ((size_t)bh*256 + obase + u)*128 + tl*8;
    *(float4*)dst     = make_float4(acc[u][0],acc[u][1],acc[u][2],acc[u][3]);
    *(float4*)(dst+4) = make_float4(acc[u][4],acc[u][5],acc[u][6],acc[u][7]);
    float ls=0.f, lq=0.f;
    #pragma unroll
    for (int v=0;v<8;v++){ ls += acc[u][v]; lq += acc[u][v]*acc[u][v]; }
    s[u]=ls; q[u]=lq;
  }
  #pragma unroll
  for (int off=8; off>0; off>>=1){
    #pragma unroll
    for (int u=0;u<8;u++){
      s[u] += __shfl_down_sync(0xffffffffu, s[u], off, 16);
      q[u] += __shfl_down_sync(0xffffffffu, q[u], off, 16);
    }
  }
  if (tl == 0){
    #pragma unroll
    for (int u=0;u<8;u++){
      atomicAdd(&g_qkv_sum[obase+u], s[u]);
      atomicAdd(&g_qkv_sq [obase+u], q[u]);
    }
  }
}

// ---------------- K2: finalize qkv BN ----------------
__global__ void k_fin_qkv(const float* __restrict__ gm, const float* __restrict__ bt){
  int o = threadIdx.x;
  float m = g_qkv_sum[o] * (1.f/16384.f);
  float v = g_qkv_sq[o] * (1.f/16384.f) - m*m;
  float a = gm[o] * rsqrtf(v + EPSV);
  g_qkv_a[o] = a;
  g_qkv_b[o] = bt[o] - m*a;
}

// ---------------- K3: qe/ke build + tf32x3 tensor GEMM + sim stats ----------
// grid (16,128), 256 threads = 8 warps. Warp tile 32(m) x 64(n).
// qe/ke stored hi/lo tf32 transposed [i][x_chunk] pitch 68, x chunked by 64.
__global__ __launch_bounds__(256) void k_qk(const float* __restrict__ rel){
  extern __shared__ float sm[];
  float* qeh = sm;              // [128][68]
  float* qel = qeh + 128*68;
  float* keh = qel + 128*68;
  float* kel = keh + 128*68;
  float* re  = kel + 128*68;    // [8][256]
  float* qn  = re  + 8*256;     // [8][128]
  float* red = qn  + 1024;      // 64
  const int g = blockIdx.x, bh = blockIdx.y;
  const int tid = threadIdx.x;
  const int w = tid>>5, ln = tid&31;

  for (int idx = tid; idx < 8*255; idx += 256)
    re[(idx/255)*256 + (idx%255)] = rel[idx];
  for (int idx = tid; idx < 1024; idx += 256){
    int a = idx >> 7, xx = idx & 127;
    int o = g*16 + a;       // a<4: q channels, 4..7: k channels
    qn[idx] = g_qkv[((size_t)bh*256 + o)*128 + xx] * g_qkv_a[o] + g_qkv_b[o];
  }
  __syncthreads();

  const int wm = (w>>1)*32, wn = (w&1)*64;
  const int r4 = ln>>2, c4 = ln&3;
  float acc[2][8][4];
  #pragma unroll
  for (int mi=0;mi<2;mi++)
    #pragma unroll
    for (int ni=0;ni<8;ni++)
      #pragma unroll
      for (int q=0;q<4;q++) acc[mi][ni][q]=0.f;

  float sqe=0.f,qqe=0.f,ske=0.f,qke=0.f;

  for (int chunk = 0; chunk < 2; chunk++){
    // build qe/ke hi/lo for x in [chunk*64, chunk*64+64)
    for (int idx = tid; idx < 64*128; idx += 256){
      int xl = idx & 63, i = idx >> 6;
      int x = chunk*64 + xl;
      int off = x - i + 127;
      float e1 = 0.f, e2 = 0.f;
      #pragma unroll
      for (int a=0;a<4;a++){
        e1 = fmaf(qn[a*128+x],     re[a*256+off],     e1);
        e2 = fmaf(qn[(4+a)*128+x], re[(4+a)*256+off], e2);
      }
      sqe += e1; qqe += e1*e1; ske += e2; qke += e2*e2;
      unsigned h1 = cvt_tf32(e1);
      unsigned h2 = cvt_tf32(e2);
      float hf1 = __uint_as_float(h1), hf2 = __uint_as_float(h2);
      qeh[i*68+xl] = hf1;
      qel[i*68+xl] = __uint_as_float(cvt_tf32(e1 - hf1));
      keh[i*68+xl] = hf2;
      kel[i*68+xl] = __uint_as_float(cvt_tf32(e2 - hf2));
    }
    __syncthreads();
    // MMA over this 64-wide k chunk: 8 k-steps of 8
    for (int kk = 0; kk < 8; kk++){
      int xk = kk*8;
      unsigned ah[2][4], al[2][4];
      #pragma unroll
      for (int mi=0;mi<2;mi++){
        const float* p = qeh + (wm + mi*16 + r4)*68 + xk + c4;
        ah[mi][0]=__float_as_uint(p[0]);
        ah[mi][1]=__float_as_uint(p[8*68]);
        ah[mi][2]=__float_as_uint(p[4]);
        ah[mi][3]=__float_as_uint(p[8*68+4]);
        const float* pl = p + 128*68;   // qel
        al[mi][0]=__float_as_uint(pl[0]);
        al[mi][1]=__float_as_uint(pl[8*68]);
        al[mi][2]=__float_as_uint(pl[4]);
        al[mi][3]=__float_as_uint(pl[8*68+4]);
      }
      #pragma unroll
      for (int ni=0;ni<8;ni++){
        const float* pb = keh + (wn + ni*8 + r4)*68 + xk + c4;
        unsigned bhv[2] = {__float_as_uint(pb[0]), __float_as_uint(pb[4])};
        const float* pbl = pb + 128*68; // kel
        unsigned blv[2] = {__float_as_uint(pbl[0]), __float_as_uint(pbl[4])};
        #pragma unroll
        for (int mi=0;mi<2;mi++){
          mma8(acc[mi][ni], ah[mi], bhv);
          mma8(acc[mi][ni], ah[mi], blv);
          mma8(acc[mi][ni], al[mi], bhv);
        }
      }
    }
    __syncthreads();  // before next chunk's build overwrites smem
  }

  // qe/ke stats
  #pragma unroll
  for (int off=16; off>0; off>>=1){
    sqe += __shfl_down_sync(0xffffffffu, sqe, off);
    qqe += __shfl_down_sync(0xffffffffu, qqe, off);
    ske += __shfl_down_sync(0xffffffffu, ske, off);
    qke += __shfl_down_sync(0xffffffffu, qke, off);
  }
  if (ln==0){ red[w]=sqe; red[8+w]=qqe; red[16+w]=ske; red[24+w]=qke; }

  // store qk + qk stats
  float* dst0 = g_qk + ((size_t)(bh*16+g))*16384;
  float sqk=0.f, qqk=0.f;
  #pragma unroll
  for (int mi=0;mi<2;mi++){
    int i0 = wm + mi*16 + r4;
    #pragma unroll
    for (int ni=0;ni<8;ni++){
      int j0 = wn + ni*8 + 2*c4;
      float* a4 = acc[mi][ni];
      *(float2*)(dst0 + (size_t)i0*128 + j0)     = make_float2(a4[0],a4[1]);
      *(float2*)(dst0 + (size_t)(i0+8)*128 + j0) = make_float2(a4[2],a4[3]);
      sqk += a4[0]+a4[1]+a4[2]+a4[3];
      qqk += a4[0]*a4[0]+a4[1]*a4[1]+a4[2]*a4[2]+a4[3]*a4[3];
    }
  }
  #pragma unroll
  for (int off=16; off>0; off>>=1){
    sqk += __shfl_down_sync(0xffffffffu, sqk, off);
    qqk += __shfl_down_sync(0xffffffffu, qqk, off);
  }
  __syncthreads();
  if (ln==0){ red[32+w]=sqk; red[40+w]=qqk; }
  __syncthreads();
  if (tid==0){
    float t0=0,t1=0,t2=0,t3=0,t4=0,t5=0;
    for (int k2=0;k2<8;k2++){
      t0+=red[k2]; t1+=red[8+k2]; t2+=red[16+k2];
      t3+=red[24+k2]; t4+=red[32+k2]; t5+=red[40+k2];
    }
    atomicAdd(&g_sim_sum[16+g], t0); atomicAdd(&g_sim_sq[16+g], t1);
    atomicAdd(&g_sim_sum[32+g], t2); atomicAdd(&g_sim_sq[32+g], t3);
    atomicAdd(&g_sim_sum[g],    t4); atomicAdd(&g_sim_sq[g],    t5);
  }
}

// ---------------- K4: finalize sim BN scales (means cancel in softmax) ---------
__global__ void k_fin_sim(const float* __restrict__ gm){
  int c = threadIdx.x;
  if (c < 48){
    const float ninv = 1.f/2097152.f;
    float m = g_sim_sum[c]*ninv;
    float v = g_sim_sq[c]*ninv - m*m;
    g_sim_scale[c] = gm[c]*rsqrtf(v+EPSV);
  }
}

// ---------------- K5: softmax + am/ame + out stats ----------------
// grid (16, 128). 8 warps; warp w owns rows i = w*16..w*16+15.
// Lane ln owns j in {ln, ln+32, ln+64, ln+96} -> conflict-free smem.
__global__ __launch_bounds__(256) void k_attn(const float* __restrict__ rel){
  extern __shared__ float sm[];
  float* re    = sm;            // [16][256]
  float* qn    = re + 16*256;   // [8][128]  q(0-3), k(4-7) normalized
  float* stage = qn + 1024;     // 8 warps * 16*36
  const int g = blockIdx.x, bh = blockIdx.y;
  const int tid = threadIdx.x;
  const int w = tid>>5, ln = tid&31;
  for (int idx = tid; idx < 16*255; idx += 256)
    re[(idx/255)*256 + (idx%255)] = rel[idx];
  for (int idx = tid; idx < 1024; idx += 256){
    int a = idx >> 7, xx = idx & 127;
    int oq = g*16 + a;
    qn[idx] = g_qkv[((size_t)bh*256 + oq)*128 + xx]*g_qkv_a[oq] + g_qkv_b[oq];
  }
  __syncthreads();
  // V normalized, row-invariant per lane: vv[c][t] = v[c][ln+32t]
  float vv[8][4];
  #pragma unroll
  for (int c=0;c<8;c++){
    int ov = g*16 + 8 + c;
    float a = g_qkv_a[ov], b = g_qkv_b[ov];
    const float* src = g_qkv + ((size_t)bh*256 + ov)*128 + ln;
    #pragma unroll
    for (int t=0;t<4;t++) vv[c][t] = src[32*t]*a + b;
  }
  const float s0 = g_sim_scale[g], s1 = g_sim_scale[16+g], s2 = g_sim_scale[32+g];
  const float* qkrow0 = g_qk + ((size_t)(bh*16+g))*16384;
  float* st = stage + w*(16*36);
  float outbuf[16];
  float osum = 0.f, osq = 0.f;
  for (int r = 0; r < 16; r++){
    const int i = w*16 + r;
    float qi[4], ki[4];
    #pragma unroll
    for (int a=0;a<4;a++){ qi[a]=qn[a*128+i]; ki[a]=qn[(4+a)*128+i]; }
    float p[4]; float mx = -1e30f;
    #pragma unroll
    for (int t=0;t<4;t++){
      int j = ln + 32*t;
      int off = i - j + 127;
      float e1=0.f, e2=0.f;
      #pragma unroll
      for (int a=0;a<4;a++){
        e1 = fmaf(qi[a], re[a*256+off],     e1);
        e2 = fmaf(ki[a], re[(4+a)*256+off], e2);
      }
      float lg = qkrow0[(size_t)i*128 + j]*s0 + e1*s1 + e2*s2;
      p[t] = lg;
      mx = fmaxf(mx, lg);
    }
    #pragma unroll
    for (int o2=16; o2>0; o2>>=1) mx = fmaxf(mx, __shfl_xor_sync(0xffffffffu, mx, o2));
    float ss = 0.f;
    #pragma unroll
    for (int t=0;t<4;t++){ p[t] = __expf(p[t]-mx); ss += p[t]; }
    #pragma unroll
    for (int o2=16; o2>0; o2>>=1) ss += __shfl_xor_sync(0xffffffffu, ss, o2);
    float inv = 1.f/ss;
    #pragma unroll
    for (int t=0;t<4;t++) p[t] *= inv;
    // partial am/ame over this lane's 4 j's
    #pragma unroll
    for (int c=0;c<8;c++){
      float am=0.f, ae=0.f;
      #pragma unroll
      for (int t=0;t<4;t++){
        int j = ln + 32*t;
        am = fmaf(p[t], vv[c][t], am);
        ae = fmaf(p[t], re[(8+c)*256 + (i-j+127)], ae);
      }
      st[(2*c)*36   + ln] = am;
      st[(2*c+1)*36 + ln] = ae;
    }
    __syncwarp();
    if (ln < 16){
      const float4* rowp = (const float4*)(st + ln*36);
      float4 v0 = rowp[0], v1 = rowp[1], v2 = rowp[2], v3 = rowp[3];
      float4 v4 = rowp[4], v5 = rowp[5], v6 = rowp[6], v7 = rowp[7];
      float outv = ((v0.x+v0.y+v0.z+v0.w) + (v1.x+v1.y+v1.z+v1.w))
                 + ((v2.x+v2.y+v2.z+v2.w) + (v3.x+v3.y+v3.z+v3.w))
                 + ((v4.x+v4.y+v4.z+v4.w) + (v5.x+v5.y+v5.z+v5.w))
                 + ((v6.x+v6.y+v6.z+v6.w) + (v7.x+v7.y+v7.z+v7.w));
      outbuf[r] = outv;
      osum += outv; osq += outv*outv;
    }
    __syncwarp();
  }
  if (ln < 16){
    float* dst = g_O + ((size_t)bh*256 + g*16 + ln)*128 + w*16;
    #pragma unroll
    for (int r4=0;r4<4;r4++)
      *(float4*)(dst + r4*4) = make_float4(outbuf[r4*4],outbuf[r4*4+1],outbuf[r4*4+2],outbuf[r4*4+3]);
    atomicAdd(&g_out_sum[g*16+ln], osum);
    atomicAdd(&g_out_sq [g*16+ln], osq);
  }
}

// ---------------- K6: finalize out BN ----------------
__global__ void k_fin_out(const float* __restrict__ gm, const float* __restrict__ bt){
  int o = threadIdx.x;
  float m = g_out_sum[o]*(1.f/16384.f);
  float v = g_out_sq[o]*(1.f/16384.f) - m*m;
  float a = gm[o]*rsqrtf(v+EPSV);
  g_out_a[o]=a; g_out_b[o]=bt[o]-m*a;
}

// ---------------- K7: normalize, pair-sum, transpose to (B,128,H,W) -----------
__global__ __launch_bounds__(256) void k_final(float* __restrict__ out){
  int t = blockIdx.x*256 + threadIdx.x;      // one float4 per thread
  int lq = t & 31;
  int h  = (t>>5) & 63;
  int m  = (t>>11) & 127;
  int b  = (t>>18) & 1;
  int bh = b*64 + h;
  int ch = 2*m;
  const float4 am = *(const float4*)(g_O + ((size_t)bh*256 + ch  )*128 + lq*4);
  const float4 ae = *(const float4*)(g_O + ((size_t)bh*256 + ch+1)*128 + lq*4);
  float a0=g_out_a[ch], b0=g_out_b[ch], a1=g_out_a[ch+1], b1=g_out_b[ch+1];
  float4 rr;
  rr.x = fmaf(am.x,a0,b0) + fmaf(ae.x,a1,b1);
  rr.y = fmaf(am.y,a0,b0) + fmaf(ae.y,a1,b1);
  rr.z = fmaf(am.z,a0,b0) + fmaf(ae.z,a1,b1);
  rr.w = fmaf(am.w,a0,b0) + fmaf(ae.w,a1,b1);
  ((float4*)out)[t] = rr;
}

// ---------------- host launcher ----------------
extern "C" void kernel_launch(void* const* d_in, const int* in_sizes, int n_in,
                              void* d_out, int out_size){
  (void)in_sizes; (void)n_in; (void)out_size;
  const float* x  = (const float*)d_in[0];
  const float* Wq = (const float*)d_in[1];
  const float* gq = (const float*)d_in[2];
  const float* bq = (const float*)d_in[3];
  const float* re = (const float*)d_in[4];
  const float* gs = (const float*)d_in[5];
  // d_in[6] = beta_sim: cancels in softmax (constant in j per channel)
  const float* go = (const float*)d_in[7];
  const float* bo = (const float*)d_in[8];

  const int smem1 = 2*128*132*4;                                   // 135168
  const int smem3 = (4*128*68 + 8*256 + 8*128 + 64)*4;             // 151808
  const int smem5 = (16*256 + 8*128 + 8*16*36)*4;                  // 38912
  cudaFuncSetAttribute(k_qkv, cudaFuncAttributeMaxDynamicSharedMemorySize, smem1);
  cudaFuncSetAttribute(k_qk,  cudaFuncAttributeMaxDynamicSharedMemorySize, smem3);

  k_zero   <<<1,256>>>();
  k_qkv    <<<dim3(2,128),256,smem1>>>(x, Wq);
  k_fin_qkv<<<1,256>>>(gq,bq);
  k_qk     <<<dim3(16,128),256,smem3>>>(re);
  k_fin_sim<<<1,64>>>(gs);
  k_attn   <<<dim3(16,128),256,smem5>>>(re);
  k_fin_out<<<1,256>>>(go,bo);
  k_final  <<<2048,256>>>((float*)d_out);
}

// round 7
// speedup vs baseline: 1.5472x; 1.1596x over previous
#include <cuda_runtime.h>
#include <math.h>

#define EPSV 1e-5f

// ---------------- scratch (static device allocations only) ----------------
__device__ float g_qkv[128*256*128];          // [bh][o][l]        16 MB
__device__ float g_qk[128*16*128*128];        // [bh*16+g][i][j]  134 MB
__device__ float g_O[128*256*128];            // [bh][ch2][i]      16 MB
__device__ float g_qkv_sum[256], g_qkv_sq[256];
__device__ float g_sim_sum[48],  g_sim_sq[48];
__device__ float g_out_sum[256], g_out_sq[256];
__device__ float g_qkv_a[256], g_qkv_b[256];
__device__ float g_sim_scale[48];
__device__ float g_out_a[256], g_out_b[256];

__device__ __forceinline__ unsigned cvt_tf32(float v){
  unsigned r; asm("cvt.rna.tf32.f32 %0, %1;" : "=r"(r) : "f"(v)); return r;
}
__device__ __forceinline__ void mma8(float* d, const unsigned* a, const unsigned* b){
  asm volatile("mma.sync.aligned.m16n8k8.row.col.f32.tf32.tf32.f32 "
    "{%0,%1,%2,%3},{%4,%5,%6,%7},{%8,%9},{%0,%1,%2,%3};"
    : "+f"(d[0]),"+f"(d[1]),"+f"(d[2]),"+f"(d[3])
    : "r"(a[0]),"r"(a[1]),"r"(a[2]),"r"(a[3]),"r"(b[0]),"r"(b[1]));
}

// ---------------- K0: zero stats ----------------
__global__ void k_zero(){
  int t = threadIdx.x;
  if (t < 256){ g_qkv_sum[t]=0.f; g_qkv_sq[t]=0.f; g_out_sum[t]=0.f; g_out_sq[t]=0.f; }
  if (t < 48){  g_sim_sum[t]=0.f; g_sim_sq[t]=0.f; }
}

// ---------------- K1: qkv = W_qkv @ x  (per bh), + channel stats ----------------
__global__ __launch_bounds__(256) void k_qkv(const float* __restrict__ x,
                                             const float* __restrict__ Wq){
  extern __shared__ float sm[];
  float* Ws = sm;            // [c][o_local] pitch 132
  float* Xs = sm + 128*132;  // [c][l]       pitch 132
  const int bh = blockIdx.y, ot = blockIdx.x;
  const int b = bh >> 6, h = bh & 63;
  const int tid = threadIdx.x;
  for (int idx = tid; idx < 16384; idx += 256){
    int r = idx >> 7, c2 = idx & 127;
    Ws[c2*132 + r] = Wq[(ot*128 + r)*128 + c2];
    Xs[r*132 + c2] = x[(((b*128 + r)*64) + h)*128 + c2];
  }
  __syncthreads();
  const int to = tid >> 4, tl = tid & 15;
  float acc[8][8];
  #pragma unroll
  for (int u=0;u<8;u++){
    #pragma unroll
    for (int v=0;v<8;v++) acc[u][v]=0.f;
  }
  const float* wa = Ws + to*8;
  const float* xb = Xs + tl*8;
  for (int c = 0; c < 128; c++){
    float4 A0 = *(const float4*)(wa + c*132);
    float4 A1 = *(const float4*)(wa + c*132 + 4);
    float4 B0 = *(const float4*)(xb + c*132);
    float4 B1 = *(const float4*)(xb + c*132 + 4);
    float a[8]  = {A0.x,A0.y,A0.z,A0.w,A1.x,A1.y,A1.z,A1.w};
    float bb[8] = {B0.x,B0.y,B0.z,B0.w,B1.x,B1.y,B1.z,B1.w};
    #pragma unroll
    for (int u=0;u<8;u++){
      #pragma unroll
      for (int v=0;v<8;v++) acc[u][v] = fmaf(a[u], bb[v], acc[u][v]);
    }
  }
  float s[8], q[8];
  const int obase = ot*128 + to*8;
  #pragma unroll
  for (int u=0;u<8;u++){
    float* dst = g_qkv + ((size_t)bh*256 + obase + u)*128 + tl*8;
    *(float4*)dst     = make_float4(acc[u][0],acc[u][1],acc[u][2],acc[u][3]);
    *(float4*)(dst+4) = make_float4(acc[u][4],acc[u][5],acc[u][6],acc[u][7]);
    float ls=0.f, lq=0.f;
    #pragma unroll
    for (int v=0;v<8;v++){ ls += acc[u][v]; lq += acc[u][v]*acc[u][v]; }
    s[u]=ls; q[u]=lq;
  }
  #pragma unroll
  for (int off=8; off>0; off>>=1){
    #pragma unroll
    for (int u=0;u<8;u++){
      s[u] += __shfl_down_sync(0xffffffffu, s[u], off, 16);
      q[u] += __shfl_down_sync(0xffffffffu, q[u], off, 16);
    }
  }
  if (tl == 0){
    #pragma unroll
    for (int u=0;u<8;u++){
      atomicAdd(&g_qkv_sum[obase+u], s[u]);
      atomicAdd(&g_qkv_sq [obase+u], q[u]);
    }
  }
}

// ---------------- K2: finalize qkv BN ----------------
__global__ void k_fin_qkv(const float* __restrict__ gm, const float* __restrict__ bt){
  int o = threadIdx.x;
  float m = g_qkv_sum[o] * (1.f/16384.f);
  float v = g_qkv_sq[o] * (1.f/16384.f) - m*m;
  float a = gm[o] * rsqrtf(v + EPSV);
  g_qkv_a[o] = a;
  g_qkv_b[o] = bt[o] - m*a;
}

// ---------------- K3: qe/ke build + tf32x3 tensor GEMM + sim stats ----------
// grid (16,128), 256 threads = 8 warps, 2 CTAs/SM. Warp tile 32(m) x 64(n).
// qe/ke stored hi/lo tf32 transposed [i][x_chunk] pitch 36, x chunked by 32.
__global__ __launch_bounds__(256,2) void k_qk(const float* __restrict__ rel){
  extern __shared__ float sm[];
  float* qeh = sm;              // [128][36]
  float* qel = qeh + 128*36;
  float* keh = qel + 128*36;
  float* kel = keh + 128*36;
  float* re  = kel + 128*36;    // [8][256]
  float* qn  = re  + 8*256;     // [8][128]
  float* red = qn  + 1024;      // 64
  const int g = blockIdx.x, bh = blockIdx.y;
  const int tid = threadIdx.x;
  const int w = tid>>5, ln = tid&31;

  for (int idx = tid; idx < 8*255; idx += 256)
    re[(idx/255)*256 + (idx%255)] = rel[idx];
  for (int idx = tid; idx < 1024; idx += 256){
    int a = idx >> 7, xx = idx & 127;
    int o = g*16 + a;       // a<4: q channels, 4..7: k channels
    qn[idx] = g_qkv[((size_t)bh*256 + o)*128 + xx] * g_qkv_a[o] + g_qkv_b[o];
  }
  __syncthreads();

  const int wm = (w>>1)*32, wn = (w&1)*64;
  const int r4 = ln>>2, c4 = ln&3;
  float acc[2][8][4];
  #pragma unroll
  for (int mi=0;mi<2;mi++)
    #pragma unroll
    for (int ni=0;ni<8;ni++)
      #pragma unroll
      for (int q=0;q<4;q++) acc[mi][ni][q]=0.f;

  float sqe=0.f,qqe=0.f,ske=0.f,qke=0.f;

  for (int chunk = 0; chunk < 4; chunk++){
    // build qe/ke hi/lo for x in [chunk*32, chunk*32+32)
    for (int idx = tid; idx < 32*128; idx += 256){
      int xl = idx & 31, i = idx >> 5;
      int x = chunk*32 + xl;
      int off = x - i + 127;
      float e1 = 0.f, e2 = 0.f;
      #pragma unroll
      for (int a=0;a<4;a++){
        e1 = fmaf(qn[a*128+x],     re[a*256+off],     e1);
        e2 = fmaf(qn[(4+a)*128+x], re[(4+a)*256+off], e2);
      }
      sqe += e1; qqe += e1*e1; ske += e2; qke += e2*e2;
      unsigned h1 = cvt_tf32(e1);
      unsigned h2 = cvt_tf32(e2);
      float hf1 = __uint_as_float(h1), hf2 = __uint_as_float(h2);
      qeh[i*36+xl] = hf1;
      qel[i*36+xl] = __uint_as_float(cvt_tf32(e1 - hf1));
      keh[i*36+xl] = hf2;
      kel[i*36+xl] = __uint_as_float(cvt_tf32(e2 - hf2));
    }
    __syncthreads();
    // MMA over this 32-wide k chunk: 4 k-steps of 8
    for (int kk = 0; kk < 4; kk++){
      int xk = kk*8;
      unsigned ah[2][4], al[2][4];
      #pragma unroll
      for (int mi=0;mi<2;mi++){
        const float* p = qeh + (wm + mi*16 + r4)*36 + xk + c4;
        ah[mi][0]=__float_as_uint(p[0]);
        ah[mi][1]=__float_as_uint(p[8*36]);
        ah[mi][2]=__float_as_uint(p[4]);
        ah[mi][3]=__float_as_uint(p[8*36+4]);
        const float* pl = p + 128*36;   // qel
        al[mi][0]=__float_as_uint(pl[0]);
        al[mi][1]=__float_as_uint(pl[8*36]);
        al[mi][2]=__float_as_uint(pl[4]);
        al[mi][3]=__float_as_uint(pl[8*36+4]);
      }
      #pragma unroll
      for (int ni=0;ni<8;ni++){
        const float* pb = keh + (wn + ni*8 + r4)*36 + xk + c4;
        unsigned bhv[2] = {__float_as_uint(pb[0]), __float_as_uint(pb[4])};
        const float* pbl = pb + 128*36; // kel
        unsigned blv[2] = {__float_as_uint(pbl[0]), __float_as_uint(pbl[4])};
        #pragma unroll
        for (int mi=0;mi<2;mi++){
          mma8(acc[mi][ni], ah[mi], bhv);
          mma8(acc[mi][ni], ah[mi], blv);
          mma8(acc[mi][ni], al[mi], bhv);
        }
      }
    }
    __syncthreads();  // before next chunk's build overwrites smem
  }

  // qe/ke stats
  #pragma unroll
  for (int off=16; off>0; off>>=1){
    sqe += __shfl_down_sync(0xffffffffu, sqe, off);
    qqe += __shfl_down_sync(0xffffffffu, qqe, off);
    ske += __shfl_down_sync(0xffffffffu, ske, off);
    qke += __shfl_down_sync(0xffffffffu, qke, off);
  }
  if (ln==0){ red[w]=sqe; red[8+w]=qqe; red[16+w]=ske; red[24+w]=qke; }

  // store qk + qk stats
  float* dst0 = g_qk + ((size_t)(bh*16+g))*16384;
  float sqk=0.f, qqk=0.f;
  #pragma unroll
  for (int mi=0;mi<2;mi++){
    int i0 = wm + mi*16 + r4;
    #pragma unroll
    for (int ni=0;ni<8;ni++){
      int j0 = wn + ni*8 + 2*c4;
      float* a4 = acc[mi][ni];
      *(float2*)(dst0 + (size_t)i0*128 + j0)     = make_float2(a4[0],a4[1]);
      *(float2*)(dst0 + (size_t)(i0+8)*128 + j0) = make_float2(a4[2],a4[3]);
      sqk += a4[0]+a4[1]+a4[2]+a4[3];
      qqk += a4[0]*a4[0]+a4[1]*a4[1]+a4[2]*a4[2]+a4[3]*a4[3];
    }
  }
  #pragma unroll
  for (int off=16; off>0; off>>=1){
    sqk += __shfl_down_sync(0xffffffffu, sqk, off);
    qqk += __shfl_down_sync(0xffffffffu, qqk, off);
  }
  __syncthreads();
  if (ln==0){ red[32+w]=sqk; red[40+w]=qqk; }
  __syncthreads();
  if (tid==0){
    float t0=0,t1=0,t2=0,t3=0,t4=0,t5=0;
    for (int k2=0;k2<8;k2++){
      t0+=red[k2]; t1+=red[8+k2]; t2+=red[16+k2];
      t3+=red[24+k2]; t4+=red[32+k2]; t5+=red[40+k2];
    }
    atomicAdd(&g_sim_sum[16+g], t0); atomicAdd(&g_sim_sq[16+g], t1);
    atomicAdd(&g_sim_sum[32+g], t2); atomicAdd(&g_sim_sq[32+g], t3);
    atomicAdd(&g_sim_sum[g],    t4); atomicAdd(&g_sim_sq[g],    t5);
  }
}

// ---------------- K4: finalize sim BN scales (means cancel in softmax) ---------
__global__ void k_fin_sim(const float* __restrict__ gm){
  int c = threadIdx.x;
  if (c < 48){
    const float ninv = 1.f/2097152.f;
    float m = g_sim_sum[c]*ninv;
    float v = g_sim_sq[c]*ninv - m*m;
    g_sim_scale[c] = gm[c]*rsqrtf(v+EPSV);
  }
}

// ---------------- K5: softmax + am/ame + out stats ----------------
// grid (16, 128). 8 warps; warp w owns rows i = w*16..w*16+15.
// Lane ln owns j in {ln, ln+32, ln+64, ln+96} -> conflict-free smem.
__global__ __launch_bounds__(256) void k_attn(const float* __restrict__ rel){
  extern __shared__ float sm[];
  float* re    = sm;            // [16][256]
  float* qn    = re + 16*256;   // [8][128]  q(0-3), k(4-7) normalized
  float* stage = qn + 1024;     // 8 warps * 16*36
  const int g = blockIdx.x, bh = blockIdx.y;
  const int tid = threadIdx.x;
  const int w = tid>>5, ln = tid&31;
  for (int idx = tid; idx < 16*255; idx += 256)
    re[(idx/255)*256 + (idx%255)] = rel[idx];
  for (int idx = tid; idx < 1024; idx += 256){
    int a = idx >> 7, xx = idx & 127;
    int oq = g*16 + a;
    qn[idx] = g_qkv[((size_t)bh*256 + oq)*128 + xx]*g_qkv_a[oq] + g_qkv_b[oq];
  }
  __syncthreads();
  // V normalized, row-invariant per lane: vv[c][t] = v[c][ln+32t]
  float vv[8][4];
  #pragma unroll
  for (int c=0;c<8;c++){
    int ov = g*16 + 8 + c;
    float a = g_qkv_a[ov], b = g_qkv_b[ov];
    const float* src = g_qkv + ((size_t)bh*256 + ov)*128 + ln;
    #pragma unroll
    for (int t=0;t<4;t++) vv[c][t] = src[32*t]*a + b;
  }
  const float s0 = g_sim_scale[g], s1 = g_sim_scale[16+g], s2 = g_sim_scale[32+g];
  const float* qkrow0 = g_qk + ((size_t)(bh*16+g))*16384;
  float* st = stage + w*(16*36);
  float outbuf[16];
  float osum = 0.f, osq = 0.f;
  for (int r = 0; r < 16; r++){
    const int i = w*16 + r;
    float qi[4], ki[4];
    #pragma unroll
    for (int a=0;a<4;a++){ qi[a]=qn[a*128+i]; ki[a]=qn[(4+a)*128+i]; }
    float p[4]; float mx = -1e30f;
    #pragma unroll
    for (int t=0;t<4;t++){
      int j = ln + 32*t;
      int off = i - j + 127;
      float e1=0.f, e2=0.f;
      #pragma unroll
      for (int a=0;a<4;a++){
        e1 = fmaf(qi[a], re[a*256+off],     e1);
        e2 = fmaf(ki[a], re[(4+a)*256+off], e2);
      }
      float lg = qkrow0[(size_t)i*128 + j]*s0 + e1*s1 + e2*s2;
      p[t] = lg;
      mx = fmaxf(mx, lg);
    }
    #pragma unroll
    for (int o2=16; o2>0; o2>>=1) mx = fmaxf(mx, __shfl_xor_sync(0xffffffffu, mx, o2));
    float ss = 0.f;
    #pragma unroll
    for (int t=0;t<4;t++){ p[t] = __expf(p[t]-mx); ss += p[t]; }
    #pragma unroll
    for (int o2=16; o2>0; o2>>=1) ss += __shfl_xor_sync(0xffffffffu, ss, o2);
    float inv = 1.f/ss;
    #pragma unroll
    for (int t=0;t<4;t++) p[t] *= inv;
    // partial am/ame over this lane's 4 j's
    #pragma unroll
    for (int c=0;c<8;c++){
      float am=0.f, ae=0.f;
      #pragma unroll
      for (int t=0;t<4;t++){
        int j = ln + 32*t;
        am = fmaf(p[t], vv[c][t], am);
        ae = fmaf(p[t], re[(8+c)*256 + (i-j+127)], ae);
      }
      st[(2*c)*36   + ln] = am;
      st[(2*c+1)*36 + ln] = ae;
    }
    __syncwarp();
    if (ln < 16){
      const float4* rowp = (const float4*)(st + ln*36);
      float4 v0 = rowp[0], v1 = rowp[1], v2 = rowp[2], v3 = rowp[3];
      float4 v4 = rowp[4], v5 = rowp[5], v6 = rowp[6], v7 = rowp[7];
      float outv = ((v0.x+v0.y+v0.z+v0.w) + (v1.x+v1.y+v1.z+v1.w))
                 + ((v2.x+v2.y+v2.z+v2.w) + (v3.x+v3.y+v3.z+v3.w))
                 + ((v4.x+v4.y+v4.z+v4.w) + (v5.x+v5.y+v5.z+v5.w))
                 + ((v6.x+v6.y+v6.z+v6.w) + (v7.x+v7.y+v7.z+v7.w));
      outbuf[r] = outv;
      osum += outv; osq += outv*outv;
    }
    __syncwarp();
  }
  if (ln < 16){
    float* dst = g_O + ((size_t)bh*256 + g*16 + ln)*128 + w*16;
    #pragma unroll
    for (int r4=0;r4<4;r4++)
      *(float4*)(dst + r4*4) = make_float4(outbuf[r4*4],outbuf[r4*4+1],outbuf[r4*4+2],outbuf[r4*4+3]);
    atomicAdd(&g_out_sum[g*16+ln], osum);
    atomicAdd(&g_out_sq [g*16+ln], osq);
  }
}

// ---------------- K6: finalize out BN ----------------
__global__ void k_fin_out(const float* __restrict__ gm, const float* __restrict__ bt){
  int o = threadIdx.x;
  float m = g_out_sum[o]*(1.f/16384.f);
  float v = g_out_sq[o]*(1.f/16384.f) - m*m;
  float a = gm[o]*rsqrtf(v+EPSV);
  g_out_a[o]=a; g_out_b[o]=bt[o]-m*a;
}

// ---------------- K7: normalize, pair-sum, transpose to (B,128,H,W) -----------
__global__ __launch_bounds__(256) void k_final(float* __restrict__ out){
  int t = blockIdx.x*256 + threadIdx.x;      // one float4 per thread
  int lq = t & 31;
  int h  = (t>>5) & 63;
  int m  = (t>>11) & 127;
  int b  = (t>>18) & 1;
  int bh = b*64 + h;
  int ch = 2*m;
  const float4 am = *(const float4*)(g_O + ((size_t)bh*256 + ch  )*128 + lq*4);
  const float4 ae = *(const float4*)(g_O + ((size_t)bh*256 + ch+1)*128 + lq*4);
  float a0=g_out_a[ch], b0=g_out_b[ch], a1=g_out_a[ch+1], b1=g_out_b[ch+1];
  float4 rr;
  rr.x = fmaf(am.x,a0,b0) + fmaf(ae.x,a1,b1);
  rr.y = fmaf(am.y,a0,b0) + fmaf(ae.y,a1,b1);
  rr.z = fmaf(am.z,a0,b0) + fmaf(ae.z,a1,b1);
  rr.w = fmaf(am.w,a0,b0) + fmaf(ae.w,a1,b1);
  ((float4*)out)[t] = rr;
}

// ---------------- host launcher ----------------
extern "C" void kernel_launch(void* const* d_in, const int* in_sizes, int n_in,
                              void* d_out, int out_size){
  (void)in_sizes; (void)n_in; (void)out_size;
  const float* x  = (const float*)d_in[0];
  const float* Wq = (const float*)d_in[1];
  const float* gq = (const float*)d_in[2];
  const float* bq = (const float*)d_in[3];
  const float* re = (const float*)d_in[4];
  const float* gs = (const float*)d_in[5];
  // d_in[6] = beta_sim: cancels in softmax (constant in j per channel)
  const float* go = (const float*)d_in[7];
  const float* bo = (const float*)d_in[8];

  const int smem1 = 2*128*132*4;                                   // 135168
  const int smem3 = (4*128*36 + 8*256 + 8*128 + 64)*4;             // 86272
  const int smem5 = (16*256 + 8*128 + 8*16*36)*4;                  // 38912
  cudaFuncSetAttribute(k_qkv, cudaFuncAttributeMaxDynamicSharedMemorySize, smem1);
  cudaFuncSetAttribute(k_qk,  cudaFuncAttributeMaxDynamicSharedMemorySize, smem3);

  k_zero   <<<1,256>>>();
  k_qkv    <<<dim3(2,128),256,smem1>>>(x, Wq);
  k_fin_qkv<<<1,256>>>(gq,bq);
  k_qk     <<<dim3(16,128),256,smem3>>>(re);
  k_fin_sim<<<1,64>>>(gs);
  k_attn   <<<dim3(16,128),256,smem5>>>(re);
  k_fin_out<<<1,256>>>(go,bo);
  k_final  <<<2048,256>>>((float*)d_out);
}

// round 8
// speedup vs baseline: 1.6910x; 1.0929x over previous
#include <cuda_runtime.h>
#include <math.h>

#define EPSV 1e-5f

// ---------------- scratch (static device allocations only) ----------------
__device__ float g_qkv[128*256*128];          // [bh][o][l]        16 MB
__device__ float g_qk[128*16*128*128];        // [bh*16+g][i][j]  134 MB
__device__ float g_O[128*256*128];            // [bh][ch2][i]      16 MB
__device__ float g_qkv_sum[256], g_qkv_sq[256];
__device__ float g_sim_sum[48],  g_sim_sq[48];
__device__ float g_out_sum[256], g_out_sq[256];
__device__ float g_qkv_a[256], g_qkv_b[256];
__device__ float g_sim_scale[48];
__device__ float g_out_a[256], g_out_b[256];

__device__ __forceinline__ unsigned cvt_tf32(float v){
  unsigned r; asm("cvt.rna.tf32.f32 %0, %1;" : "=r"(r) : "f"(v)); return r;
}
__device__ __forceinline__ void mma8(float* d, const unsigned* a, const unsigned* b){
  asm volatile("mma.sync.aligned.m16n8k8.row.col.f32.tf32.tf32.f32 "
    "{%0,%1,%2,%3},{%4,%5,%6,%7},{%8,%9},{%0,%1,%2,%3};"
    : "+f"(d[0]),"+f"(d[1]),"+f"(d[2]),"+f"(d[3])
    : "r"(a[0]),"r"(a[1]),"r"(a[2]),"r"(a[3]),"r"(b[0]),"r"(b[1]));
}

// ---------------- K0: zero stats ----------------
__global__ void k_zero(){
  int t = threadIdx.x;
  if (t < 256){ g_qkv_sum[t]=0.f; g_qkv_sq[t]=0.f; g_out_sum[t]=0.f; g_out_sq[t]=0.f; }
  if (t < 48){  g_sim_sum[t]=0.f; g_sim_sq[t]=0.f; }
}

// ---------------- K1: qkv = W_qkv @ x  (per bh), + channel stats ----------------
__global__ __launch_bounds__(256) void k_qkv(const float* __restrict__ x,
                                             const float* __restrict__ Wq){
  extern __shared__ float sm[];
  float* Ws = sm;            // [c][o_local] pitch 132
  float* Xs = sm + 128*132;  // [c][l]       pitch 132
  const int bh = blockIdx.y, ot = blockIdx.x;
  const int b = bh >> 6, h = bh & 63;
  const int tid = threadIdx.x;
  for (int idx = tid; idx < 16384; idx += 256){
    int r = idx >> 7, c2 = idx & 127;
    Ws[c2*132 + r] = Wq[(ot*128 + r)*128 + c2];
    Xs[r*132 + c2] = x[(((b*128 + r)*64) + h)*128 + c2];
  }
  __syncthreads();
  const int to = tid >> 4, tl = tid & 15;
  float acc[8][8];
  #pragma unroll
  for (int u=0;u<8;u++){
    #pragma unroll
    for (int v=0;v<8;v++) acc[u][v]=0.f;
  }
  const float* wa = Ws + to*8;
  const float* xb = Xs + tl*8;
  for (int c = 0; c < 128; c++){
    float4 A0 = *(const float4*)(wa + c*132);
    float4 A1 = *(const float4*)(wa + c*132 + 4);
    float4 B0 = *(const float4*)(xb + c*132);
    float4 B1 = *(const float4*)(xb + c*132 + 4);
    float a[8]  = {A0.x,A0.y,A0.z,A0.w,A1.x,A1.y,A1.z,A1.w};
    float bb[8] = {B0.x,B0.y,B0.z,B0.w,B1.x,B1.y,B1.z,B1.w};
    #pragma unroll
    for (int u=0;u<8;u++){
      #pragma unroll
      for (int v=0;v<8;v++) acc[u][v] = fmaf(a[u], bb[v], acc[u][v]);
    }
  }
  float s[8], q[8];
  const int obase = ot*128 + to*8;
  #pragma unroll
  for (int u=0;u<8;u++){
    float* dst = g_qkv + ((size_t)bh*256 + obase + u)*128 + tl*8;
    *(float4*)dst     = make_float4(acc[u][0],acc[u][1],acc[u][2],acc[u][3]);
    *(float4*)(dst+4) = make_float4(acc[u][4],acc[u][5],acc[u][6],acc[u][7]);
    float ls=0.f, lq=0.f;
    #pragma unroll
    for (int v=0;v<8;v++){ ls += acc[u][v]; lq += acc[u][v]*acc[u][v]; }
    s[u]=ls; q[u]=lq;
  }
  #pragma unroll
  for (int off=8; off>0; off>>=1){
    #pragma unroll
    for (int u=0;u<8;u++){
      s[u] += __shfl_down_sync(0xffffffffu, s[u], off, 16);
      q[u] += __shfl_down_sync(0xffffffffu, q[u], off, 16);
    }
  }
  if (tl == 0){
    #pragma unroll
    for (int u=0;u<8;u++){
      atomicAdd(&g_qkv_sum[obase+u], s[u]);
      atomicAdd(&g_qkv_sq [obase+u], q[u]);
    }
  }
}

// ---------------- K2: finalize qkv BN ----------------
__global__ void k_fin_qkv(const float* __restrict__ gm, const float* __restrict__ bt){
  int o = threadIdx.x;
  float m = g_qkv_sum[o] * (1.f/16384.f);
  float v = g_qkv_sq[o] * (1.f/16384.f) - m*m;
  float a = gm[o] * rsqrtf(v + EPSV);
  g_qkv_a[o] = a;
  g_qkv_b[o] = bt[o] - m*a;
}

// ---------------- K3: qe/ke build + tf32x3 tensor GEMM + sim stats ----------
// grid (16,128), 256 threads = 8 warps, 2 CTAs/SM. Warp tile 32(m) x 64(n).
// qe/ke stored as interleaved hi/lo float2, [i][x_chunk] pitch 36 (x chunk 32).
// rel-emb transposed: ret[off][a] pitch 12, float4-loadable, conflict-free.
__global__ __launch_bounds__(256,2) void k_qk(const float* __restrict__ rel){
  extern __shared__ float sm[];
  float2* qehl = (float2*)sm;            // [128][36] {hi,lo}
  float2* kehl = (float2*)(sm + 9216);   // [128][36] {hi,lo}
  float*  ret  = sm + 18432;             // [255][12] channels 0..7
  float*  qn   = sm + 21492;             // [8][128]
  float*  red  = sm + 22516;             // 64
  const int g = blockIdx.x, bh = blockIdx.y;
  const int tid = threadIdx.x;
  const int w = tid>>5, ln = tid&31;

  for (int idx = tid; idx < 2040; idx += 256){
    int a = idx/255, off = idx%255;
    ret[off*12 + a] = rel[idx];
  }
  for (int idx = tid; idx < 1024; idx += 256){
    int a = idx >> 7, xx = idx & 127;
    int o = g*16 + a;       // a<4: q channels, 4..7: k channels
    qn[idx] = g_qkv[((size_t)bh*256 + o)*128 + xx] * g_qkv_a[o] + g_qkv_b[o];
  }
  __syncthreads();

  const int wm = (w>>1)*32, wn = (w&1)*64;
  const int r4 = ln>>2, c4 = ln&3;
  float acc[2][8][4];
  #pragma unroll
  for (int mi=0;mi<2;mi++)
    #pragma unroll
    for (int ni=0;ni<8;ni++)
      #pragma unroll
      for (int q=0;q<4;q++) acc[mi][ni][q]=0.f;

  float sqe=0.f,qqe=0.f,ske=0.f,qke=0.f;
  const int xl = tid & 31;      // per-thread x lane (fixed within chunk)
  const int i0 = tid >> 5;      // warp id = base row

  for (int chunk = 0; chunk < 4; chunk++){
    const int x = chunk*32 + xl;
    // hoist qn loads: invariant over i
    float q8[8];
    #pragma unroll
    for (int a=0;a<8;a++) q8[a] = qn[a*128 + x];
    // build qe/ke hi/lo for this x, rows i0, i0+8, ..., i0+120
    #pragma unroll 4
    for (int ii = 0; ii < 16; ii++){
      int i = i0 + ii*8;
      int off = x - i + 127;
      const float4 ra = *(const float4*)(ret + off*12);
      const float4 rb = *(const float4*)(ret + off*12 + 4);
      float e1 = fmaf(q8[0],ra.x, fmaf(q8[1],ra.y, fmaf(q8[2],ra.z, q8[3]*ra.w)));
      float e2 = fmaf(q8[4],rb.x, fmaf(q8[5],rb.y, fmaf(q8[6],rb.z, q8[7]*rb.w)));
      sqe += e1; qqe += e1*e1; ske += e2; qke += e2*e2;
      float hf1 = __uint_as_float(cvt_tf32(e1));
      float hf2 = __uint_as_float(cvt_tf32(e2));
      qehl[i*36+xl] = make_float2(hf1, __uint_as_float(cvt_tf32(e1 - hf1)));
      kehl[i*36+xl] = make_float2(hf2, __uint_as_float(cvt_tf32(e2 - hf2)));
    }
    __syncthreads();
    // MMA over this 32-wide k chunk: 4 k-steps of 8
    for (int kk = 0; kk < 4; kk++){
      int xk = kk*8;
      unsigned ah[2][4], al[2][4];
      #pragma unroll
      for (int mi=0;mi<2;mi++){
        const float2* p = qehl + (wm + mi*16 + r4)*36 + xk + c4;
        float2 v00 = p[0], v10 = p[8*36], v01 = p[4], v11 = p[8*36+4];
        ah[mi][0]=__float_as_uint(v00.x); al[mi][0]=__float_as_uint(v00.y);
        ah[mi][1]=__float_as_uint(v10.x); al[mi][1]=__float_as_uint(v10.y);
        ah[mi][2]=__float_as_uint(v01.x); al[mi][2]=__float_as_uint(v01.y);
        ah[mi][3]=__float_as_uint(v11.x); al[mi][3]=__float_as_uint(v11.y);
      }
      #pragma unroll
      for (int ni=0;ni<8;ni++){
        const float2* pb = kehl + (wn + ni*8 + r4)*36 + xk + c4;
        float2 b0 = pb[0], b1 = pb[4];
        unsigned bhv[2] = {__float_as_uint(b0.x), __float_as_uint(b1.x)};
        unsigned blv[2] = {__float_as_uint(b0.y), __float_as_uint(b1.y)};
        #pragma unroll
        for (int mi=0;mi<2;mi++){
          mma8(acc[mi][ni], ah[mi], bhv);
          mma8(acc[mi][ni], ah[mi], blv);
          mma8(acc[mi][ni], al[mi], bhv);
        }
      }
    }
    __syncthreads();  // before next chunk's build overwrites smem
  }

  // qe/ke stats
  #pragma unroll
  for (int off=16; off>0; off>>=1){
    sqe += __shfl_down_sync(0xffffffffu, sqe, off);
    qqe += __shfl_down_sync(0xffffffffu, qqe, off);
    ske += __shfl_down_sync(0xffffffffu, ske, off);
    qke += __shfl_down_sync(0xffffffffu, qke, off);
  }
  if (ln==0){ red[w]=sqe; red[8+w]=qqe; red[16+w]=ske; red[24+w]=qke; }

  // store qk + qk stats
  float* dst0 = g_qk + ((size_t)(bh*16+g))*16384;
  float sqk=0.f, qqk=0.f;
  #pragma unroll
  for (int mi=0;mi<2;mi++){
    int i0s = wm + mi*16 + r4;
    #pragma unroll
    for (int ni=0;ni<8;ni++){
      int j0 = wn + ni*8 + 2*c4;
      float* a4 = acc[mi][ni];
      *(float2*)(dst0 + (size_t)i0s*128 + j0)     = make_float2(a4[0],a4[1]);
      *(float2*)(dst0 + (size_t)(i0s+8)*128 + j0) = make_float2(a4[2],a4[3]);
      sqk += a4[0]+a4[1]+a4[2]+a4[3];
      qqk += a4[0]*a4[0]+a4[1]*a4[1]+a4[2]*a4[2]+a4[3]*a4[3];
    }
  }
  #pragma unroll
  for (int off=16; off>0; off>>=1){
    sqk += __shfl_down_sync(0xffffffffu, sqk, off);
    qqk += __shfl_down_sync(0xffffffffu, qqk, off);
  }
  __syncthreads();
  if (ln==0){ red[32+w]=sqk; red[40+w]=qqk; }
  __syncthreads();
  if (tid==0){
    float t0=0,t1=0,t2=0,t3=0,t4=0,t5=0;
    for (int k2=0;k2<8;k2++){
      t0+=red[k2]; t1+=red[8+k2]; t2+=red[16+k2];
      t3+=red[24+k2]; t4+=red[32+k2]; t5+=red[40+k2];
    }
    atomicAdd(&g_sim_sum[16+g], t0); atomicAdd(&g_sim_sq[16+g], t1);
    atomicAdd(&g_sim_sum[32+g], t2); atomicAdd(&g_sim_sq[32+g], t3);
    atomicAdd(&g_sim_sum[g],    t4); atomicAdd(&g_sim_sq[g],    t5);
  }
}

// ---------------- K4: finalize sim BN scales (means cancel in softmax) ---------
__global__ void k_fin_sim(const float* __restrict__ gm){
  int c = threadIdx.x;
  if (c < 48){
    const float ninv = 1.f/2097152.f;
    float m = g_sim_sum[c]*ninv;
    float v = g_sim_sq[c]*ninv - m*m;
    g_sim_scale[c] = gm[c]*rsqrtf(v+EPSV);
  }
}

// ---------------- K5: softmax + am/ame + out stats ----------------
// grid (16, 128). 8 warps; warp w owns rows i = w*16..w*16+15.
// Lane ln owns j in {ln, ln+32, ln+64, ln+96}. rel-emb transposed for float4 loads.
__global__ __launch_bounds__(256) void k_attn(const float* __restrict__ rel){
  extern __shared__ float sm[];
  float* ret   = sm;            // [255][12] channels 0..7  (q/k emb)
  float* rv    = sm + 3060;     // [255][12] channels 8..15 (v emb)
  float* qn    = sm + 6120;     // [8][128]  q(0-3), k(4-7) normalized
  float* stage = sm + 7144;     // 8 warps * 16*36
  const int g = blockIdx.x, bh = blockIdx.y;
  const int tid = threadIdx.x;
  const int w = tid>>5, ln = tid&31;
  for (int idx = tid; idx < 2040; idx += 256){
    int a = idx/255, off = idx%255;
    ret[off*12 + a] = rel[idx];
    rv [off*12 + a] = rel[2040 + idx];
  }
  for (int idx = tid; idx < 1024; idx += 256){
    int a = idx >> 7, xx = idx & 127;
    int oq = g*16 + a;
    qn[idx] = g_qkv[((size_t)bh*256 + oq)*128 + xx]*g_qkv_a[oq] + g_qkv_b[oq];
  }
  __syncthreads();
  // V normalized, row-invariant per lane: vv[c][t] = v[c][ln+32t]
  float vv[8][4];
  #pragma unroll
  for (int c=0;c<8;c++){
    int ov = g*16 + 8 + c;
    float a = g_qkv_a[ov], b = g_qkv_b[ov];
    const float* src = g_qkv + ((size_t)bh*256 + ov)*128 + ln;
    #pragma unroll
    for (int t=0;t<4;t++) vv[c][t] = src[32*t]*a + b;
  }
  const float s0 = g_sim_scale[g], s1 = g_sim_scale[16+g], s2 = g_sim_scale[32+g];
  const float* qkrow0 = g_qk + ((size_t)(bh*16+g))*16384;
  float* st = stage + w*(16*36);
  float outbuf[16];
  float osum = 0.f, osq = 0.f;
  for (int r = 0; r < 16; r++){
    const int i = w*16 + r;
    float qi[4], ki[4];
    #pragma unroll
    for (int a=0;a<4;a++){ qi[a]=qn[a*128+i]; ki[a]=qn[(4+a)*128+i]; }
    float p[4]; float mx = -1e30f;
    int offs[4];
    #pragma unroll
    for (int t=0;t<4;t++){
      int j = ln + 32*t;
      int off = i - j + 127;
      offs[t] = off;
      const float4 ra = *(const float4*)(ret + off*12);
      const float4 rb = *(const float4*)(ret + off*12 + 4);
      float e1 = fmaf(qi[0],ra.x, fmaf(qi[1],ra.y, fmaf(qi[2],ra.z, qi[3]*ra.w)));
      float e2 = fmaf(ki[0],rb.x, fmaf(ki[1],rb.y, fmaf(ki[2],rb.z, ki[3]*rb.w)));
      float lg = qkrow0[(size_t)i*128 + j]*s0 + e1*s1 + e2*s2;
      p[t] = lg;
      mx = fmaxf(mx, lg);
    }
    #pragma unroll
    for (int o2=16; o2>0; o2>>=1) mx = fmaxf(mx, __shfl_xor_sync(0xffffffffu, mx, o2));
    float ss = 0.f;
    #pragma unroll
    for (int t=0;t<4;t++){ p[t] = __expf(p[t]-mx); ss += p[t]; }
    #pragma unroll
    for (int o2=16; o2>0; o2>>=1) ss += __shfl_xor_sync(0xffffffffu, ss, o2);
    float inv = 1.f/ss;
    #pragma unroll
    for (int t=0;t<4;t++) p[t] *= inv;
    // partial am/ame over this lane's 4 j's
    float av[8], ac[8];
    #pragma unroll
    for (int c=0;c<8;c++){ av[c]=0.f; ac[c]=0.f; }
    #pragma unroll
    for (int t=0;t<4;t++){
      const float4 v1 = *(const float4*)(rv + offs[t]*12);
      const float4 v2 = *(const float4*)(rv + offs[t]*12 + 4);
      float pt = p[t];
      av[0] = fmaf(pt, vv[0][t], av[0]);
      av[1] = fmaf(pt, vv[1][t], av[1]);
      av[2] = fmaf(pt, vv[2][t], av[2]);
      av[3] = fmaf(pt, vv[3][t], av[3]);
      av[4] = fmaf(pt, vv[4][t], av[4]);
      av[5] = fmaf(pt, vv[5][t], av[5]);
      av[6] = fmaf(pt, vv[6][t], av[6]);
      av[7] = fmaf(pt, vv[7][t], av[7]);
      ac[0] = fmaf(pt, v1.x, ac[0]);
      ac[1] = fmaf(pt, v1.y, ac[1]);
      ac[2] = fmaf(pt, v1.z, ac[2]);
      ac[3] = fmaf(pt, v1.w, ac[3]);
      ac[4] = fmaf(pt, v2.x, ac[4]);
      ac[5] = fmaf(pt, v2.y, ac[5]);
      ac[6] = fmaf(pt, v2.z, ac[6]);
      ac[7] = fmaf(pt, v2.w, ac[7]);
    }
    #pragma unroll
    for (int c=0;c<8;c++){
      st[(2*c)*36   + ln] = av[c];
      st[(2*c+1)*36 + ln] = ac[c];
    }
    __syncwarp();
    if (ln < 16){
      const float4* rowp = (const float4*)(st + ln*36);
      float4 v0 = rowp[0], v1 = rowp[1], v2 = rowp[2], v3 = rowp[3];
      float4 v4 = rowp[4], v5 = rowp[5], v6 = rowp[6], v7 = rowp[7];
      float outv = ((v0.x+v0.y+v0.z+v0.w) + (v1.x+v1.y+v1.z+v1.w))
                 + ((v2.x+v2.y+v2.z+v2.w) + (v3.x+v3.y+v3.z+v3.w))
                 + ((v4.x+v4.y+v4.z+v4.w) + (v5.x+v5.y+v5.z+v5.w))
                 + ((v6.x+v6.y+v6.z+v6.w) + (v7.x+v7.y+v7.z+v7.w));
      outbuf[r] = outv;
      osum += outv; osq += outv*outv;
    }
    __syncwarp();
  }
  if (ln < 16){
    float* dst = g_O + ((size_t)bh*256 + g*16 + ln)*128 + w*16;
    #pragma unroll
    for (int r4=0;r4<4;r4++)
      *(float4*)(dst + r4*4) = make_float4(outbuf[r4*4],outbuf[r4*4+1],outbuf[r4*4+2],outbuf[r4*4+3]);
    atomicAdd(&g_out_sum[g*16+ln], osum);
    atomicAdd(&g_out_sq [g*16+ln], osq);
  }
}

// ---------------- K6: finalize out BN ----------------
__global__ void k_fin_out(const float* __restrict__ gm, const float* __restrict__ bt){
  int o = threadIdx.x;
  float m = g_out_sum[o]*(1.f/16384.f);
  float v = g_out_sq[o]*(1.f/16384.f) - m*m;
  float a = gm[o]*rsqrtf(v+EPSV);
  g_out_a[o]=a; g_out_b[o]=bt[o]-m*a;
}

// ---------------- K7: normalize, pair-sum, transpose to (B,128,H,W) -----------
__global__ __launch_bounds__(256) void k_final(float* __restrict__ out){
  int t = blockIdx.x*256 + threadIdx.x;      // one float4 per thread
  int lq = t & 31;
  int h  = (t>>5) & 63;
  int m  = (t>>11) & 127;
  int b  = (t>>18) & 1;
  int bh = b*64 + h;
  int ch = 2*m;
  const float4 am = *(const float4*)(g_O + ((size_t)bh*256 + ch  )*128 + lq*4);
  const float4 ae = *(const float4*)(g_O + ((size_t)bh*256 + ch+1)*128 + lq*4);
  float a0=g_out_a[ch], b0=g_out_b[ch], a1=g_out_a[ch+1], b1=g_out_b[ch+1];
  float4 rr;
  rr.x = fmaf(am.x,a0,b0) + fmaf(ae.x,a1,b1);
  rr.y = fmaf(am.y,a0,b0) + fmaf(ae.y,a1,b1);
  rr.z = fmaf(am.z,a0,b0) + fmaf(ae.z,a1,b1);
  rr.w = fmaf(am.w,a0,b0) + fmaf(ae.w,a1,b1);
  ((float4*)out)[t] = rr;
}

// ---------------- host launcher ----------------
extern "C" void kernel_launch(void* const* d_in, const int* in_sizes, int n_in,
                              void* d_out, int out_size){
  (void)in_sizes; (void)n_in; (void)out_size;
  const float* x  = (const float*)d_in[0];
  const float* Wq = (const float*)d_in[1];
  const float* gq = (const float*)d_in[2];
  const float* bq = (const float*)d_in[3];
  const float* re = (const float*)d_in[4];
  const float* gs = (const float*)d_in[5];
  // d_in[6] = beta_sim: cancels in softmax (constant in j per channel)
  const float* go = (const float*)d_in[7];
  const float* bo = (const float*)d_in[8];

  const int smem1 = 2*128*132*4;                                   // 135168
  const int smem3 = (2*2*128*36 + 255*12 + 8*128 + 64)*4;          // 90320
  const int smem5 = (2*255*12 + 8*128 + 8*16*36)*4;                // 47008
  cudaFuncSetAttribute(k_qkv, cudaFuncAttributeMaxDynamicSharedMemorySize, smem1);
  cudaFuncSetAttribute(k_qk,  cudaFuncAttributeMaxDynamicSharedMemorySize, smem3);

  k_zero   <<<1,256>>>();
  k_qkv    <<<dim3(2,128),256,smem1>>>(x, Wq);
  k_fin_qkv<<<1,256>>>(gq,bq);
  k_qk     <<<dim3(16,128),256,smem3>>>(re);
  k_fin_sim<<<1,64>>>(gs);
  k_attn   <<<dim3(16,128),256,smem5>>>(re);
  k_fin_out<<<1,256>>>(go,bo);
  k_final  <<<2048,256>>>((float*)d_out);
}